// round 5
// baseline (speedup 1.0000x reference)
#include <cuda_runtime.h>
#include <cstdint>

#define B_ 2
#define N_ 2048
#define L_ 2048
#define D_ 1024
#define H_ 16
#define HD_ 64
#define LOG2E 1.4426950408889634f
#define SCALE_Q (0.125f * LOG2E)   // HD^-0.5 * log2(e), folded into Q projection
#define MASKBIAS (-2.0e30f)
#define MINIT (-1.0e30f)

// Scratch (device globals: allocation-free rule)
__device__ float g_Q[(size_t)B_ * H_ * N_ * HD_];   // [bh][n][hd], pre-scaled by SCALE_Q
__device__ float g_K[(size_t)B_ * H_ * L_ * HD_];   // [bh][l][hd]
__device__ float g_V[(size_t)B_ * H_ * L_ * HD_];   // [bh][l][hd]
__device__ float g_O[(size_t)B_ * N_ * D_];         // (B*N, D) row-major
__device__ unsigned char g_mask[B_ * L_];

// ---------------------------------------------------------------------------
__device__ __forceinline__ uint32_t f2tf(float x) {
    uint32_t r;
    asm("cvt.rna.tf32.f32 %0, %1;" : "=r"(r) : "f"(x));
    return r;
}
__device__ __forceinline__ float ex2f(float x) {
    float r;
    asm("ex2.approx.ftz.f32 %0, %1;" : "=f"(r) : "f"(x));
    return r;
}
#define MMA_TF32(C, A, B)                                                        \
    asm volatile(                                                                \
        "mma.sync.aligned.m16n8k8.row.col.f32.tf32.tf32.f32 "                    \
        "{%0,%1,%2,%3},{%4,%5,%6,%7},{%8,%9},{%0,%1,%2,%3};"                     \
        : "+f"((C)[0]), "+f"((C)[1]), "+f"((C)[2]), "+f"((C)[3])                 \
        : "r"((A)[0]), "r"((A)[1]), "r"((A)[2]), "r"((A)[3]),                    \
          "r"((B)[0]), "r"((B)[1]))

// ---------------------------------------------------------------------------
// Mask canonicalization (dtype sniff) -> g_mask uint8
// ---------------------------------------------------------------------------
__global__ void mask_prep(const void* __restrict__ mraw)
{
    __shared__ int s_isfloat;
    __shared__ int s_nonbin;
    const int t = threadIdx.x;  // 1024 threads
    if (t == 0) { s_isfloat = 0; s_nonbin = 0; }
    __syncthreads();

    const int* ip = (const int*)mraw;
    int v = ip[t];
    if (v == 0x3F800000) atomicExch(&s_isfloat, 1);
    if (v != 0 && v != 1) atomicExch(&s_nonbin, 1);
    __syncthreads();

    int mode;
    if (s_isfloat) mode = 2;
    else if (s_nonbin) mode = 1;
    else mode = 0;

    const unsigned char* bp = (const unsigned char*)mraw;
    const float* fp = (const float*)mraw;
    for (int i = t; i < B_ * L_; i += 1024) {
        unsigned char mv;
        if (mode == 0)      mv = (ip[i] != 0) ? 1 : 0;
        else if (mode == 1) mv = (bp[i] != 0) ? 1 : 0;
        else                mv = (fp[i] != 0.0f) ? 1 : 0;
        g_mask[i] = mv;
    }
}

// ---------------------------------------------------------------------------
// tf32 tensor-core GEMM: C[4096,1024] = A @ W + bias (tf32 inputs, fp32 accum)
// BM=BN=128, BK=16, 256 threads = 8 warps (4 M x 2 N), warp tile 32x64.
// MODE 0: Q (head-major, *SCALE_Q)  1: K  2: V  3: out-proj (A = g_O)
// ---------------------------------------------------------------------------
#define SA 20    // As row stride (floats): 16 + 4 pad -> conflict-free frags
#define SB 132   // Bs row stride: 128 + 4

template <int MODE>
__global__ void __launch_bounds__(256)
proj_tc(const float* __restrict__ A, const float* __restrict__ W,
        const float* __restrict__ bias, float* __restrict__ Cout)
{
    __shared__ float As[128 * SA];  // [m][k]
    __shared__ float Bs[16 * SB];   // [k][n]

    const float* Ap = (MODE == 3) ? (const float*)g_O : A;
    const int tid = threadIdx.x;
    const int lane = tid & 31, wid = tid >> 5;
    const int g = lane >> 2, t = lane & 3;
    const int wm = wid & 3, wn = wid >> 2;
    const int bx = blockIdx.x, by = blockIdx.y;

    // load mapping
    const int arow = tid >> 2, akc = (tid & 3) * 4;       // A: +64 rows for q=1
    const int brow = tid >> 5, bnc = (tid & 31) * 4;      // B: +8 rows for q=1
    const float* aP0 = Ap + (size_t)(by * 128 + arow) * D_ + akc;
    const float* aP1 = aP0 + (size_t)64 * D_;
    const float* bP0 = W + (size_t)brow * D_ + bx * 128 + bnc;
    const float* bP1 = bP0 + (size_t)8 * D_;

    float c[2][8][4];
#pragma unroll
    for (int i = 0; i < 2; i++)
#pragma unroll
        for (int j = 0; j < 8; j++)
#pragma unroll
            for (int k = 0; k < 4; k++) c[i][j][k] = 0.0f;

    float4 ra0, ra1, rb0, rb1;
    // prologue: tile 0
    ra0 = *(const float4*)(aP0);
    ra1 = *(const float4*)(aP1);
    rb0 = *(const float4*)(bP0);
    rb1 = *(const float4*)(bP1);
    {
        float4 ca0, ca1, cb0, cb1;
        ca0.x = __uint_as_float(f2tf(ra0.x)); ca0.y = __uint_as_float(f2tf(ra0.y));
        ca0.z = __uint_as_float(f2tf(ra0.z)); ca0.w = __uint_as_float(f2tf(ra0.w));
        ca1.x = __uint_as_float(f2tf(ra1.x)); ca1.y = __uint_as_float(f2tf(ra1.y));
        ca1.z = __uint_as_float(f2tf(ra1.z)); ca1.w = __uint_as_float(f2tf(ra1.w));
        cb0.x = __uint_as_float(f2tf(rb0.x)); cb0.y = __uint_as_float(f2tf(rb0.y));
        cb0.z = __uint_as_float(f2tf(rb0.z)); cb0.w = __uint_as_float(f2tf(rb0.w));
        cb1.x = __uint_as_float(f2tf(rb1.x)); cb1.y = __uint_as_float(f2tf(rb1.y));
        cb1.z = __uint_as_float(f2tf(rb1.z)); cb1.w = __uint_as_float(f2tf(rb1.w));
        *(float4*)&As[arow * SA + akc]        = ca0;
        *(float4*)&As[(arow + 64) * SA + akc] = ca1;
        *(float4*)&Bs[brow * SB + bnc]        = cb0;
        *(float4*)&Bs[(brow + 8) * SB + bnc]  = cb1;
    }
    __syncthreads();

    for (int kt = 0; kt < 64; kt++) {
        // prefetch next tile to regs
        if (kt < 63) {
            size_t offA = (size_t)(kt + 1) * 16;
            size_t offB = (size_t)(kt + 1) * 16 * D_;
            ra0 = *(const float4*)(aP0 + offA);
            ra1 = *(const float4*)(aP1 + offA);
            rb0 = *(const float4*)(bP0 + offB);
            rb1 = *(const float4*)(bP1 + offB);
        }
        // compute 2 k-steps of 8
#pragma unroll
        for (int ks = 0; ks < 2; ks++) {
            const int k0 = ks * 8;
            uint32_t a[2][4];
#pragma unroll
            for (int mt = 0; mt < 2; mt++) {
                int r = wm * 32 + mt * 16 + g;
                a[mt][0] = __float_as_uint(As[r * SA + k0 + t]);
                a[mt][1] = __float_as_uint(As[(r + 8) * SA + k0 + t]);
                a[mt][2] = __float_as_uint(As[r * SA + k0 + t + 4]);
                a[mt][3] = __float_as_uint(As[(r + 8) * SA + k0 + t + 4]);
            }
#pragma unroll
            for (int nt = 0; nt < 8; nt++) {
                int n = wn * 64 + nt * 8 + g;
                uint32_t b[2];
                b[0] = __float_as_uint(Bs[(k0 + t) * SB + n]);
                b[1] = __float_as_uint(Bs[(k0 + t + 4) * SB + n]);
                MMA_TF32(c[0][nt], a[0], b);
                MMA_TF32(c[1][nt], a[1], b);
            }
        }
        __syncthreads();
        if (kt < 63) {
            float4 ca0, ca1, cb0, cb1;
            ca0.x = __uint_as_float(f2tf(ra0.x)); ca0.y = __uint_as_float(f2tf(ra0.y));
            ca0.z = __uint_as_float(f2tf(ra0.z)); ca0.w = __uint_as_float(f2tf(ra0.w));
            ca1.x = __uint_as_float(f2tf(ra1.x)); ca1.y = __uint_as_float(f2tf(ra1.y));
            ca1.z = __uint_as_float(f2tf(ra1.z)); ca1.w = __uint_as_float(f2tf(ra1.w));
            cb0.x = __uint_as_float(f2tf(rb0.x)); cb0.y = __uint_as_float(f2tf(rb0.y));
            cb0.z = __uint_as_float(f2tf(rb0.z)); cb0.w = __uint_as_float(f2tf(rb0.w));
            cb1.x = __uint_as_float(f2tf(rb1.x)); cb1.y = __uint_as_float(f2tf(rb1.y));
            cb1.z = __uint_as_float(f2tf(rb1.z)); cb1.w = __uint_as_float(f2tf(rb1.w));
            *(float4*)&As[arow * SA + akc]        = ca0;
            *(float4*)&As[(arow + 64) * SA + akc] = ca1;
            *(float4*)&Bs[brow * SB + bnc]        = cb0;
            *(float4*)&Bs[(brow + 8) * SB + bnc]  = cb1;
            __syncthreads();
        }
    }

    // epilogue
#pragma unroll
    for (int mt = 0; mt < 2; mt++) {
        int r0 = by * 128 + wm * 32 + mt * 16 + g;
        int r1 = r0 + 8;
#pragma unroll
        for (int nt = 0; nt < 8; nt++) {
            int col = bx * 128 + wn * 64 + nt * 8 + 2 * t;
            float2 bb = *(const float2*)&bias[col];
            float v00 = c[mt][nt][0] + bb.x, v01 = c[mt][nt][1] + bb.y;
            float v10 = c[mt][nt][2] + bb.x, v11 = c[mt][nt][3] + bb.y;
            if (MODE == 0) {
                v00 *= SCALE_Q; v01 *= SCALE_Q; v10 *= SCALE_Q; v11 *= SCALE_Q;
            }
            if (MODE == 3) {
                *(float2*)&Cout[(size_t)r0 * D_ + col] = make_float2(v00, v01);
                *(float2*)&Cout[(size_t)r1 * D_ + col] = make_float2(v10, v11);
            } else {
                float* dst = (MODE == 0) ? g_Q : (MODE == 1) ? g_K : g_V;
                int h = col >> 6, hd = col & 63;
                {
                    int b = r0 >> 11, n = r0 & 2047;
                    *(float2*)&dst[(((size_t)(b * H_ + h)) * 2048 + n) * HD_ + hd] =
                        make_float2(v00, v01);
                }
                {
                    int b = r1 >> 11, n = r1 & 2047;
                    *(float2*)&dst[(((size_t)(b * H_ + h)) * 2048 + n) * HD_ + hd] =
                        make_float2(v10, v11);
                }
            }
        }
    }
}

// ---------------------------------------------------------------------------
// Tensor-core flash attention (tf32 mma). CTA = (b,h) x 64-query tile.
// 128 threads = 4 warps; warp tile = 16 rows x 64 cols. KV tile = 64.
// Base-2 online softmax (LOG2E folded into Q).
// smem (dynamic): Qs[64][68] | KPs[64][68] (K then P) | Vs[64][72] | Mb[64]
// ---------------------------------------------------------------------------
#define SQ 68
#define SV 72
#define ATTN_SMEM ((64 * SQ * 2 + 64 * SV + 64) * 4)

__global__ void __launch_bounds__(128)
attn_tc()
{
    extern __shared__ float sm[];
    float* Qs  = sm;                 // 64*68
    float* KPs = Qs + 64 * SQ;       // 64*68
    float* Vs  = KPs + 64 * SQ;      // 64*72
    float* Mb  = Vs + 64 * SV;       // 64

    const int tid = threadIdx.x;
    const int lane = tid & 31, wid = tid >> 5;
    const int g = lane >> 2, t = lane & 3;
    const int bh = blockIdx.y;
    const int b = bh >> 4, h = bh & 15;
    const int qt = blockIdx.x;

    const float* Qp = g_Q + ((size_t)bh * N_ + qt * 64) * HD_;
    const float* Kp = g_K + (size_t)bh * L_ * HD_;
    const float* Vp = g_V + (size_t)bh * L_ * HD_;
    const unsigned char* mp = g_mask + b * L_;

    // load Q (cvt to tf32)
#pragma unroll
    for (int q = 0; q < 8; q++) {
        int idx = tid + 128 * q;
        int row = idx >> 4, kc = (idx & 15) * 4;
        float4 v = *(const float4*)(Qp + (size_t)row * HD_ + kc);
        float4 cv;
        cv.x = __uint_as_float(f2tf(v.x)); cv.y = __uint_as_float(f2tf(v.y));
        cv.z = __uint_as_float(f2tf(v.z)); cv.w = __uint_as_float(f2tf(v.w));
        *(float4*)&Qs[row * SQ + kc] = cv;
    }

    float m0 = MINIT, m1 = MINIT, l0 = 0.0f, l1 = 0.0f;
    float oc[8][4];
#pragma unroll
    for (int nt = 0; nt < 8; nt++)
#pragma unroll
        for (int j = 0; j < 4; j++) oc[nt][j] = 0.0f;

    const int r = wid * 16 + g;   // warp-local row (and r+8)

    for (int tt = 0; tt < L_ / 64; tt++) {
        __syncthreads();  // prev iter done with KPs/Vs/Mb; also Q visible (tt=0)

        // load K, V tiles (cvt), mask bias
#pragma unroll
        for (int q = 0; q < 8; q++) {
            int idx = tid + 128 * q;
            int row = idx >> 4, kc = (idx & 15) * 4;
            float4 kv = *(const float4*)(Kp + (size_t)(tt * 64 + row) * HD_ + kc);
            float4 ck;
            ck.x = __uint_as_float(f2tf(kv.x)); ck.y = __uint_as_float(f2tf(kv.y));
            ck.z = __uint_as_float(f2tf(kv.z)); ck.w = __uint_as_float(f2tf(kv.w));
            *(float4*)&KPs[row * SQ + kc] = ck;
            float4 vv = *(const float4*)(Vp + (size_t)(tt * 64 + row) * HD_ + kc);
            float4 cv;
            cv.x = __uint_as_float(f2tf(vv.x)); cv.y = __uint_as_float(f2tf(vv.y));
            cv.z = __uint_as_float(f2tf(vv.z)); cv.w = __uint_as_float(f2tf(vv.w));
            *(float4*)&Vs[row * SV + kc] = cv;
        }
        if (tid < 16) {
            uchar4 mv = *(const uchar4*)(mp + tt * 64 + tid * 4);
            Mb[tid * 4 + 0] = mv.x ? MASKBIAS : 0.0f;
            Mb[tid * 4 + 1] = mv.y ? MASKBIAS : 0.0f;
            Mb[tid * 4 + 2] = mv.z ? MASKBIAS : 0.0f;
            Mb[tid * 4 + 3] = mv.w ? MASKBIAS : 0.0f;
        }
        __syncthreads();

        // S = Q K^T (already log2e-scaled via Q)
        float sc[8][4];
#pragma unroll
        for (int nt = 0; nt < 8; nt++)
#pragma unroll
            for (int j = 0; j < 4; j++) sc[nt][j] = 0.0f;

#pragma unroll
        for (int ks = 0; ks < 8; ks++) {
            const int k0 = ks * 8;
            uint32_t aq[4];
            aq[0] = __float_as_uint(Qs[r * SQ + k0 + t]);
            aq[1] = __float_as_uint(Qs[(r + 8) * SQ + k0 + t]);
            aq[2] = __float_as_uint(Qs[r * SQ + k0 + t + 4]);
            aq[3] = __float_as_uint(Qs[(r + 8) * SQ + k0 + t + 4]);
#pragma unroll
            for (int nt = 0; nt < 8; nt++) {
                int n = nt * 8 + g;
                uint32_t bk[2];
                bk[0] = __float_as_uint(KPs[n * SQ + k0 + t]);
                bk[1] = __float_as_uint(KPs[n * SQ + k0 + t + 4]);
                MMA_TF32(sc[nt], aq, bk);
            }
        }

        // mask bias
#pragma unroll
        for (int nt = 0; nt < 8; nt++) {
            float2 mb = *(const float2*)&Mb[nt * 8 + 2 * t];
            sc[nt][0] += mb.x; sc[nt][1] += mb.y;
            sc[nt][2] += mb.x; sc[nt][3] += mb.y;
        }

        // row max (rows g and g+8 of warp tile)
        float tm0 = -3.0e38f, tm1 = -3.0e38f;
#pragma unroll
        for (int nt = 0; nt < 8; nt++) {
            tm0 = fmaxf(tm0, fmaxf(sc[nt][0], sc[nt][1]));
            tm1 = fmaxf(tm1, fmaxf(sc[nt][2], sc[nt][3]));
        }
        tm0 = fmaxf(tm0, __shfl_xor_sync(0xffffffffu, tm0, 1));
        tm0 = fmaxf(tm0, __shfl_xor_sync(0xffffffffu, tm0, 2));
        tm1 = fmaxf(tm1, __shfl_xor_sync(0xffffffffu, tm1, 1));
        tm1 = fmaxf(tm1, __shfl_xor_sync(0xffffffffu, tm1, 2));

        float mn0 = fmaxf(m0, tm0), mn1 = fmaxf(m1, tm1);
        float al0 = ex2f(m0 - mn0), al1 = ex2f(m1 - mn1);
        m0 = mn0; m1 = mn1;

        float rs0 = 0.0f, rs1 = 0.0f;
#pragma unroll
        for (int nt = 0; nt < 8; nt++) {
            sc[nt][0] = ex2f(sc[nt][0] - mn0);
            sc[nt][1] = ex2f(sc[nt][1] - mn0);
            sc[nt][2] = ex2f(sc[nt][2] - mn1);
            sc[nt][3] = ex2f(sc[nt][3] - mn1);
            rs0 += sc[nt][0] + sc[nt][1];
            rs1 += sc[nt][2] + sc[nt][3];
        }
        rs0 += __shfl_xor_sync(0xffffffffu, rs0, 1);
        rs0 += __shfl_xor_sync(0xffffffffu, rs0, 2);
        rs1 += __shfl_xor_sync(0xffffffffu, rs1, 1);
        rs1 += __shfl_xor_sync(0xffffffffu, rs1, 2);
        l0 = l0 * al0 + rs0;
        l1 = l1 * al1 + rs1;
#pragma unroll
        for (int nt = 0; nt < 8; nt++) {
            oc[nt][0] *= al0; oc[nt][1] *= al0;
            oc[nt][2] *= al1; oc[nt][3] *= al1;
        }

        __syncthreads();  // all warps done reading K before P overwrites
#pragma unroll
        for (int nt = 0; nt < 8; nt++) {
            int cc = nt * 8 + 2 * t;
            float2 p0 = make_float2(__uint_as_float(f2tf(sc[nt][0])),
                                    __uint_as_float(f2tf(sc[nt][1])));
            float2 p1 = make_float2(__uint_as_float(f2tf(sc[nt][2])),
                                    __uint_as_float(f2tf(sc[nt][3])));
            *(float2*)&KPs[r * SQ + cc] = p0;
            *(float2*)&KPs[(r + 8) * SQ + cc] = p1;
        }
        __syncthreads();

        // O += P V
#pragma unroll
        for (int ks = 0; ks < 8; ks++) {
            const int k0 = ks * 8;
            uint32_t ap[4];
            ap[0] = __float_as_uint(KPs[r * SQ + k0 + t]);
            ap[1] = __float_as_uint(KPs[(r + 8) * SQ + k0 + t]);
            ap[2] = __float_as_uint(KPs[r * SQ + k0 + t + 4]);
            ap[3] = __float_as_uint(KPs[(r + 8) * SQ + k0 + t + 4]);
#pragma unroll
            for (int nt = 0; nt < 8; nt++) {
                int n = nt * 8 + g;
                uint32_t bv[2];
                bv[0] = __float_as_uint(Vs[(k0 + t) * SV + n]);
                bv[1] = __float_as_uint(Vs[(k0 + t + 4) * SV + n]);
                MMA_TF32(oc[nt], ap, bv);
            }
        }
    }

    // epilogue: normalize and write head-major into g_O (B*N, D)
    float inv0 = 1.0f / l0, inv1 = 1.0f / l1;
    int n0 = qt * 64 + r, n1 = n0 + 8;
#pragma unroll
    for (int nt = 0; nt < 8; nt++) {
        int cc = nt * 8 + 2 * t;
        *(float2*)&g_O[((size_t)(b * N_ + n0)) * D_ + h * HD_ + cc] =
            make_float2(oc[nt][0] * inv0, oc[nt][1] * inv0);
        *(float2*)&g_O[((size_t)(b * N_ + n1)) * D_ + h * HD_ + cc] =
            make_float2(oc[nt][2] * inv1, oc[nt][3] * inv1);
    }
}

// ---------------------------------------------------------------------------
extern "C" void kernel_launch(void* const* d_in, const int* in_sizes, int n_in,
                              void* d_out, int out_size)
{
    (void)in_sizes; (void)n_in; (void)out_size;
    const float* x_q  = (const float*)d_in[0];
    const float* x_kv = (const float*)d_in[1];
    const void*  mraw = d_in[2];
    const float* wq = (const float*)d_in[3];
    const float* bq = (const float*)d_in[4];
    const float* wk = (const float*)d_in[5];
    const float* bk = (const float*)d_in[6];
    const float* wv = (const float*)d_in[7];
    const float* bv = (const float*)d_in[8];
    const float* wo = (const float*)d_in[9];
    const float* bo = (const float*)d_in[10];
    float* out = (float*)d_out;

    static int attr_done = 0;
    if (!attr_done) {
        cudaFuncSetAttribute(attn_tc, cudaFuncAttributeMaxDynamicSharedMemorySize,
                             ATTN_SMEM);
        attr_done = 1;
    }

    mask_prep<<<1, 1024>>>(mraw);

    dim3 gg(D_ / 128, (B_ * N_) / 128);  // (8, 32)
    proj_tc<0><<<gg, 256>>>(x_q, wq, bq, nullptr);
    proj_tc<1><<<gg, 256>>>(x_kv, wk, bk, nullptr);
    proj_tc<2><<<gg, 256>>>(x_kv, wv, bv, nullptr);

    attn_tc<<<dim3(N_ / 64, B_ * H_), 128, ATTN_SMEM>>>();

    proj_tc<3><<<gg, 256>>>(nullptr, wo, bo, out);
}

// round 7
// speedup vs baseline: 1.2017x; 1.2017x over previous
#include <cuda_runtime.h>
#include <cstdint>

#define B_ 2
#define N_ 2048
#define L_ 2048
#define D_ 1024
#define H_ 16
#define HD_ 64
#define LOG2E 1.4426950408889634f
#define SCALE_Q (0.125f * LOG2E)
#define MASKBIAS (-2.0e30f)
#define MINIT (-1.0e30f)

__device__ float g_Q[(size_t)B_ * H_ * N_ * HD_];
__device__ float g_K[(size_t)B_ * H_ * L_ * HD_];
__device__ float g_V[(size_t)B_ * H_ * L_ * HD_];
__device__ float g_O[(size_t)B_ * N_ * D_];
__device__ unsigned char g_mask[B_ * L_];

__device__ __forceinline__ uint32_t f2tf(float x) {
    uint32_t r; asm("cvt.rna.tf32.f32 %0, %1;" : "=r"(r) : "f"(x)); return r;
}
__device__ __forceinline__ float ex2f(float x) {
    float r; asm("ex2.approx.ftz.f32 %0, %1;" : "=f"(r) : "f"(x)); return r;
}
__device__ __forceinline__ float4 cvt4(float4 v) {
    return make_float4(__uint_as_float(f2tf(v.x)), __uint_as_float(f2tf(v.y)),
                       __uint_as_float(f2tf(v.z)), __uint_as_float(f2tf(v.w)));
}
#define MMA_TF32(C, A, Bf) \
    asm volatile("mma.sync.aligned.m16n8k8.row.col.f32.tf32.tf32.f32 " \
        "{%0,%1,%2,%3},{%4,%5,%6,%7},{%8,%9},{%0,%1,%2,%3};" \
        : "+f"((C)[0]), "+f"((C)[1]), "+f"((C)[2]), "+f"((C)[3]) \
        : "r"((A)[0]), "r"((A)[1]), "r"((A)[2]), "r"((A)[3]), "r"((Bf)[0]), "r"((Bf)[1]))

// ---------------------------------------------------------------------------
__global__ void mask_prep(const void* __restrict__ mraw)
{
    __shared__ int s_isf, s_nb;
    const int t = threadIdx.x;
    if (t == 0) { s_isf = 0; s_nb = 0; }
    __syncthreads();
    const int* ip = (const int*)mraw;
    int v = ip[t];
    if (v == 0x3F800000) atomicExch(&s_isf, 1);
    if (v != 0 && v != 1) atomicExch(&s_nb, 1);
    __syncthreads();
    int mode = s_isf ? 2 : (s_nb ? 1 : 0);
    const unsigned char* bp = (const unsigned char*)mraw;
    const float* fp = (const float*)mraw;
    for (int i = t; i < B_ * L_; i += 1024) {
        unsigned char mv;
        if (mode == 0)      mv = ip[i] != 0;
        else if (mode == 1) mv = bp[i] != 0;
        else                mv = fp[i] != 0.0f;
        g_mask[i] = mv;
    }
}

// ---------------------------------------------------------------------------
// tf32 mma.sync GEMM, warp tile 64x64: C[4096,1024] = A @ W + bias.
// CTA 128(M) x 256(N), BK=16, 256 threads = 8 warps (2m x 4n).
// MODE 0:Q(*SCALE_Q, head-major) 1:K 2:V 3:out-proj (A = g_O).
// ---------------------------------------------------------------------------
#define SA 20
#define SB 264

template <int MODE>
__global__ void __launch_bounds__(256, 1)
proj64(const float* __restrict__ A, const float* __restrict__ W,
       const float* __restrict__ bias, float* __restrict__ Cout)
{
    __shared__ float As[128 * SA];
    __shared__ float Bs[16 * SB];

    const float* Ap = (MODE == 3) ? (const float*)g_O : A;
    const int tid = threadIdx.x;
    const int lane = tid & 31;
    const int wid = tid >> 5;
    const int g = lane >> 2, t = lane & 3;
    const int wm = wid & 1, wn = wid >> 1;
    const int m0 = blockIdx.y * 128, n0 = blockIdx.x * 256;

    const int arow = tid >> 2, akc = (tid & 3) * 4;
    const int brow = tid >> 6, bnc = (tid & 63) * 4;
    const float* aP0 = Ap + (size_t)(m0 + arow) * D_ + akc;
    const float* aP1 = aP0 + (size_t)64 * D_;
    const float* bP = W + (size_t)brow * D_ + n0 + bnc;

    float c[4][8][4];
#pragma unroll
    for (int i = 0; i < 4; i++)
#pragma unroll
        for (int j = 0; j < 8; j++)
#pragma unroll
            for (int k = 0; k < 4; k++) c[i][j][k] = 0.0f;

    float4 ra0 = *(const float4*)aP0;
    float4 ra1 = *(const float4*)aP1;
    float4 rb[4];
#pragma unroll
    for (int q = 0; q < 4; q++) rb[q] = *(const float4*)(bP + (size_t)(4 * q) * D_);

    for (int kt = 0; kt < 64; kt++) {
        *(float4*)&As[arow * SA + akc]        = cvt4(ra0);
        *(float4*)&As[(arow + 64) * SA + akc] = cvt4(ra1);
#pragma unroll
        for (int q = 0; q < 4; q++)
            *(float4*)&Bs[(brow + 4 * q) * SB + bnc] = cvt4(rb[q]);
        __syncthreads();
        if (kt < 63) {
            size_t oA = (size_t)(kt + 1) * 16;
            ra0 = *(const float4*)(aP0 + oA);
            ra1 = *(const float4*)(aP1 + oA);
#pragma unroll
            for (int q = 0; q < 4; q++)
                rb[q] = *(const float4*)(bP + (size_t)((kt + 1) * 16 + 4 * q) * D_);
        }
#pragma unroll
        for (int ks = 0; ks < 2; ks++) {
            const int k0 = ks * 8;
            uint32_t a[4][4];
#pragma unroll
            for (int mt = 0; mt < 4; mt++) {
                int r = wm * 64 + mt * 16 + g;
                a[mt][0] = __float_as_uint(As[r * SA + k0 + t]);
                a[mt][1] = __float_as_uint(As[(r + 8) * SA + k0 + t]);
                a[mt][2] = __float_as_uint(As[r * SA + k0 + t + 4]);
                a[mt][3] = __float_as_uint(As[(r + 8) * SA + k0 + t + 4]);
            }
#pragma unroll
            for (int nt = 0; nt < 8; nt++) {
                int n = wn * 64 + nt * 8 + g;
                uint32_t b[2];
                b[0] = __float_as_uint(Bs[(k0 + t) * SB + n]);
                b[1] = __float_as_uint(Bs[(k0 + t + 4) * SB + n]);
                MMA_TF32(c[0][nt], a[0], b);
                MMA_TF32(c[1][nt], a[1], b);
                MMA_TF32(c[2][nt], a[2], b);
                MMA_TF32(c[3][nt], a[3], b);
            }
        }
        __syncthreads();
    }

    // epilogue
#pragma unroll
    for (int mt = 0; mt < 4; mt++) {
        int r0 = m0 + wm * 64 + mt * 16 + g;
        int r1 = r0 + 8;
#pragma unroll
        for (int nt = 0; nt < 8; nt++) {
            int col = n0 + wn * 64 + nt * 8 + 2 * t;
            float2 bb = *(const float2*)&bias[col];
            float v00 = c[mt][nt][0] + bb.x, v01 = c[mt][nt][1] + bb.y;
            float v10 = c[mt][nt][2] + bb.x, v11 = c[mt][nt][3] + bb.y;
            if (MODE == 0) {
                v00 *= SCALE_Q; v01 *= SCALE_Q; v10 *= SCALE_Q; v11 *= SCALE_Q;
            }
            if (MODE == 3) {
                *(float2*)&Cout[(size_t)r0 * D_ + col] = make_float2(v00, v01);
                *(float2*)&Cout[(size_t)r1 * D_ + col] = make_float2(v10, v11);
            } else {
                float* dst = (MODE == 0) ? g_Q : (MODE == 1) ? g_K : g_V;
                int hh = col >> 6, hd = col & 63;
                {
                    int bb2 = r0 >> 11, n = r0 & 2047;
                    *(float2*)&dst[(((size_t)(bb2 * H_ + hh)) * 2048 + n) * HD_ + hd] =
                        make_float2(v00, v01);
                }
                {
                    int bb2 = r1 >> 11, n = r1 & 2047;
                    *(float2*)&dst[(((size_t)(bb2 * H_ + hh)) * 2048 + n) * HD_ + hd] =
                        make_float2(v10, v11);
                }
            }
        }
    }
}

// ---------------------------------------------------------------------------
// Flash attention: CTA = 128 queries x (b,h); 4 warps, warp tile 32q x 64kv.
// KV tile 64, per-warp private P buffers, 2 block syncs per iteration.
// smem: Qs[128][68] | Ks[64][68] | Vs[64][72] | Ps[4][32][68] | Mb[64]
// ---------------------------------------------------------------------------
#define SQ 68
#define SV 72
#define PWS (32 * SQ)
#define ATTN_SMEM ((128 * SQ + 64 * SQ + 64 * SV + 4 * PWS + 64) * 4)

__global__ void __launch_bounds__(128, 2)
attn2()
{
    extern __shared__ float sm[];
    float* Qs = sm;                  // 128*68
    float* Ks = Qs + 128 * SQ;       // 64*68
    float* Vs = Ks + 64 * SQ;        // 64*72
    float* Ps = Vs + 64 * SV;        // 4*32*68
    float* Mb = Ps + 4 * PWS;        // 64

    const int tid = threadIdx.x;
    const int lane = tid & 31, wid = tid >> 5;
    const int g = lane >> 2, t = lane & 3;
    const int bh = blockIdx.y;
    const int b = bh >> 4, h = bh & 15;
    const int qt = blockIdx.x;

    const float* Qp = g_Q + ((size_t)bh * N_ + qt * 128) * HD_;
    const float* Kp = g_K + (size_t)bh * L_ * HD_;
    const float* Vp = g_V + (size_t)bh * L_ * HD_;
    const unsigned char* mp = g_mask + b * L_;

    // load Q (128 rows x 64, cvt to tf32)
#pragma unroll
    for (int q = 0; q < 16; q++) {
        int idx = tid + 128 * q;
        int row = idx >> 4, kc = (idx & 15) * 4;
        *(float4*)&Qs[row * SQ + kc] = cvt4(*(const float4*)(Qp + (size_t)row * HD_ + kc));
    }

    float m[4], l[4];
    float oc[2][8][4];
#pragma unroll
    for (int s = 0; s < 4; s++) { m[s] = MINIT; l[s] = 0.0f; }
#pragma unroll
    for (int mt = 0; mt < 2; mt++)
#pragma unroll
        for (int nt = 0; nt < 8; nt++)
#pragma unroll
            for (int j = 0; j < 4; j++) oc[mt][nt][j] = 0.0f;

    const int R = wid * 32;
    float* Pw = Ps + wid * PWS;

    for (int tt = 0; tt < L_ / 64; tt++) {
        __syncthreads();  // prev iter done reading Ks/Vs/Mb (and Qs visible @tt=0)
#pragma unroll
        for (int q = 0; q < 8; q++) {
            int idx = tid + 128 * q;
            int row = idx >> 4, kc = (idx & 15) * 4;
            *(float4*)&Ks[row * SQ + kc] =
                cvt4(*(const float4*)(Kp + (size_t)(tt * 64 + row) * HD_ + kc));
            *(float4*)&Vs[row * SV + kc] =
                cvt4(*(const float4*)(Vp + (size_t)(tt * 64 + row) * HD_ + kc));
        }
        if (tid < 16) {
            uchar4 mv = *(const uchar4*)(mp + tt * 64 + tid * 4);
            Mb[tid * 4 + 0] = mv.x ? MASKBIAS : 0.0f;
            Mb[tid * 4 + 1] = mv.y ? MASKBIAS : 0.0f;
            Mb[tid * 4 + 2] = mv.z ? MASKBIAS : 0.0f;
            Mb[tid * 4 + 3] = mv.w ? MASKBIAS : 0.0f;
        }
        __syncthreads();

        // S = Q K^T
        float sc[2][8][4];
#pragma unroll
        for (int mt = 0; mt < 2; mt++)
#pragma unroll
            for (int nt = 0; nt < 8; nt++)
#pragma unroll
                for (int j = 0; j < 4; j++) sc[mt][nt][j] = 0.0f;
#pragma unroll
        for (int ks = 0; ks < 8; ks++) {
            const int k0 = ks * 8;
            uint32_t aq[2][4];
#pragma unroll
            for (int mt = 0; mt < 2; mt++) {
                int r = R + mt * 16 + g;
                aq[mt][0] = __float_as_uint(Qs[r * SQ + k0 + t]);
                aq[mt][1] = __float_as_uint(Qs[(r + 8) * SQ + k0 + t]);
                aq[mt][2] = __float_as_uint(Qs[r * SQ + k0 + t + 4]);
                aq[mt][3] = __float_as_uint(Qs[(r + 8) * SQ + k0 + t + 4]);
            }
#pragma unroll
            for (int nt = 0; nt < 8; nt++) {
                int n = nt * 8 + g;
                uint32_t bk[2];
                bk[0] = __float_as_uint(Ks[n * SQ + k0 + t]);
                bk[1] = __float_as_uint(Ks[n * SQ + k0 + t + 4]);
                MMA_TF32(sc[0][nt], aq[0], bk);
                MMA_TF32(sc[1][nt], aq[1], bk);
            }
        }

        // mask bias
#pragma unroll
        for (int nt = 0; nt < 8; nt++) {
            float2 mb = *(const float2*)&Mb[nt * 8 + 2 * t];
#pragma unroll
            for (int mt = 0; mt < 2; mt++) {
                sc[mt][nt][0] += mb.x; sc[mt][nt][1] += mb.y;
                sc[mt][nt][2] += mb.x; sc[mt][nt][3] += mb.y;
            }
        }

        // per-row max across tile; rows s = mt*2 + hi
        float tm[4];
#pragma unroll
        for (int s = 0; s < 4; s++) tm[s] = -3.0e38f;
#pragma unroll
        for (int mt = 0; mt < 2; mt++)
#pragma unroll
            for (int nt = 0; nt < 8; nt++) {
                tm[mt * 2 + 0] = fmaxf(tm[mt * 2 + 0], fmaxf(sc[mt][nt][0], sc[mt][nt][1]));
                tm[mt * 2 + 1] = fmaxf(tm[mt * 2 + 1], fmaxf(sc[mt][nt][2], sc[mt][nt][3]));
            }
#pragma unroll
        for (int off = 1; off < 4; off <<= 1)
#pragma unroll
            for (int s = 0; s < 4; s++)
                tm[s] = fmaxf(tm[s], __shfl_xor_sync(0xffffffffu, tm[s], off));

        float al[4], rs[4];
#pragma unroll
        for (int s = 0; s < 4; s++) {
            float mn = fmaxf(m[s], tm[s]);
            al[s] = ex2f(m[s] - mn);
            m[s] = mn;
            rs[s] = 0.0f;
        }
#pragma unroll
        for (int mt = 0; mt < 2; mt++)
#pragma unroll
            for (int nt = 0; nt < 8; nt++) {
                sc[mt][nt][0] = ex2f(sc[mt][nt][0] - m[mt * 2 + 0]);
                sc[mt][nt][1] = ex2f(sc[mt][nt][1] - m[mt * 2 + 0]);
                sc[mt][nt][2] = ex2f(sc[mt][nt][2] - m[mt * 2 + 1]);
                sc[mt][nt][3] = ex2f(sc[mt][nt][3] - m[mt * 2 + 1]);
                rs[mt * 2 + 0] += sc[mt][nt][0] + sc[mt][nt][1];
                rs[mt * 2 + 1] += sc[mt][nt][2] + sc[mt][nt][3];
            }
#pragma unroll
        for (int off = 1; off < 4; off <<= 1)
#pragma unroll
            for (int s = 0; s < 4; s++)
                rs[s] += __shfl_xor_sync(0xffffffffu, rs[s], off);
#pragma unroll
        for (int s = 0; s < 4; s++) l[s] = l[s] * al[s] + rs[s];
#pragma unroll
        for (int mt = 0; mt < 2; mt++)
#pragma unroll
            for (int nt = 0; nt < 8; nt++) {
                oc[mt][nt][0] *= al[mt * 2 + 0]; oc[mt][nt][1] *= al[mt * 2 + 0];
                oc[mt][nt][2] *= al[mt * 2 + 1]; oc[mt][nt][3] *= al[mt * 2 + 1];
            }

        // P store into per-warp buffer (warp-local, no block sync)
#pragma unroll
        for (int mt = 0; mt < 2; mt++)
#pragma unroll
            for (int nt = 0; nt < 8; nt++) {
                int cc = nt * 8 + 2 * t;
                int lr = mt * 16 + g;
                *(float2*)&Pw[lr * SQ + cc] = make_float2(
                    __uint_as_float(f2tf(sc[mt][nt][0])), __uint_as_float(f2tf(sc[mt][nt][1])));
                *(float2*)&Pw[(lr + 8) * SQ + cc] = make_float2(
                    __uint_as_float(f2tf(sc[mt][nt][2])), __uint_as_float(f2tf(sc[mt][nt][3])));
            }
        __syncwarp();

        // O += P V
#pragma unroll
        for (int ks = 0; ks < 8; ks++) {
            const int k0 = ks * 8;
            uint32_t ap[2][4];
#pragma unroll
            for (int mt = 0; mt < 2; mt++) {
                int lr = mt * 16 + g;
                ap[mt][0] = __float_as_uint(Pw[lr * SQ + k0 + t]);
                ap[mt][1] = __float_as_uint(Pw[(lr + 8) * SQ + k0 + t]);
                ap[mt][2] = __float_as_uint(Pw[lr * SQ + k0 + t + 4]);
                ap[mt][3] = __float_as_uint(Pw[(lr + 8) * SQ + k0 + t + 4]);
            }
#pragma unroll
            for (int nt = 0; nt < 8; nt++) {
                int n = nt * 8 + g;
                uint32_t bv[2];
                bv[0] = __float_as_uint(Vs[(k0 + t) * SV + n]);
                bv[1] = __float_as_uint(Vs[(k0 + t + 4) * SV + n]);
                MMA_TF32(oc[0][nt], ap[0], bv);
                MMA_TF32(oc[1][nt], ap[1], bv);
            }
        }
    }

    // epilogue: normalize, write head-major into g_O
    float inv[4];
#pragma unroll
    for (int s = 0; s < 4; s++) inv[s] = 1.0f / l[s];
#pragma unroll
    for (int mt = 0; mt < 2; mt++) {
        int n0r = qt * 128 + R + mt * 16 + g;
        int n1r = n0r + 8;
#pragma unroll
        for (int nt = 0; nt < 8; nt++) {
            int cc = nt * 8 + 2 * t;
            *(float2*)&g_O[((size_t)(b * N_ + n0r)) * D_ + h * HD_ + cc] =
                make_float2(oc[mt][nt][0] * inv[mt * 2 + 0], oc[mt][nt][1] * inv[mt * 2 + 0]);
            *(float2*)&g_O[((size_t)(b * N_ + n1r)) * D_ + h * HD_ + cc] =
                make_float2(oc[mt][nt][2] * inv[mt * 2 + 1], oc[mt][nt][3] * inv[mt * 2 + 1]);
        }
    }
}

// ---------------------------------------------------------------------------
extern "C" void kernel_launch(void* const* d_in, const int* in_sizes, int n_in,
                              void* d_out, int out_size)
{
    (void)in_sizes; (void)n_in; (void)out_size;
    const float* x_q  = (const float*)d_in[0];
    const float* x_kv = (const float*)d_in[1];
    const void*  mraw = d_in[2];
    const float* wq = (const float*)d_in[3];
    const float* bq = (const float*)d_in[4];
    const float* wk = (const float*)d_in[5];
    const float* bk = (const float*)d_in[6];
    const float* wv = (const float*)d_in[7];
    const float* bv = (const float*)d_in[8];
    const float* wo = (const float*)d_in[9];
    const float* bo = (const float*)d_in[10];
    float* out = (float*)d_out;

    static int attr_done = 0;
    if (!attr_done) {
        cudaFuncSetAttribute(attn2, cudaFuncAttributeMaxDynamicSharedMemorySize,
                             ATTN_SMEM);
        attr_done = 1;
    }

    mask_prep<<<1, 1024>>>(mraw);

    dim3 gg(D_ / 256, (B_ * N_) / 128);  // (4, 32)
    proj64<0><<<gg, 256>>>(x_q, wq, bq, nullptr);
    proj64<1><<<gg, 256>>>(x_kv, wk, bk, nullptr);
    proj64<2><<<gg, 256>>>(x_kv, wv, bv, nullptr);

    attn2<<<dim3(N_ / 128, B_ * H_), 128, ATTN_SMEM>>>();

    proj64<3><<<gg, 256>>>(nullptr, wo, bo, out);
}